// round 15
// baseline (speedup 1.0000x reference)
#include <cuda_runtime.h>
#include <cuda_fp16.h>
#include <math.h>
#include <stdint.h>

#define BB 2
#define LL 4096
#define DD 512
#define HH 8
#define DKK 64
#define MROWS (BB*LL)          // 8192
#define QKVN (3*DD)            // 1536
// softmax scale (1/sqrt(64) * log2(e)); applied inside exp2
#define CC (0.125f * 1.4426950408889634f)

// Scratch (allocation-free rule: __device__ globals)
__device__ __half g_x[(size_t)MROWS * DD];      // fp16 copy of x
__device__ __half g_wqkv[(size_t)QKVN * DD];    // fp16 copy of w_qkv
__device__ __half g_wo[(size_t)DD * DD];        // fp16 copy of w_o
__device__ __half g_qkv[(size_t)MROWS * QKVN];  // [B*L, 3*D] fp16
__device__ __half g_ctx[(size_t)MROWS * DD];    // [B*L, D]   fp16

// ---------------------------------------------------------------------------
// Helpers
// ---------------------------------------------------------------------------
__device__ __forceinline__ float ex2(float x) {
    float y;
    asm("ex2.approx.ftz.f32 %0, %1;" : "=f"(y) : "f"(x));
    return y;
}

__device__ __forceinline__ uint32_t pack_h2(float lo, float hi) {
    uint32_t r;
    asm("cvt.rn.f16x2.f32 %0, %1, %2;" : "=r"(r) : "f"(hi), "f"(lo));
    return r;
}

__device__ __forceinline__ void mma_f16(float c[4],
    uint32_t a0, uint32_t a1, uint32_t a2, uint32_t a3,
    uint32_t b0, uint32_t b1)
{
    asm volatile(
        "mma.sync.aligned.m16n8k16.row.col.f32.f16.f16.f32 "
        "{%0,%1,%2,%3}, {%4,%5,%6,%7}, {%8,%9}, {%0,%1,%2,%3};"
        : "+f"(c[0]), "+f"(c[1]), "+f"(c[2]), "+f"(c[3])
        : "r"(a0), "r"(a1), "r"(a2), "r"(a3), "r"(b0), "r"(b1));
}

__device__ __forceinline__ void ldsm4(uint32_t& r0, uint32_t& r1,
                                      uint32_t& r2, uint32_t& r3, uint32_t addr)
{
    asm volatile("ldmatrix.sync.aligned.m8n8.x4.shared.b16 {%0,%1,%2,%3}, [%4];"
                 : "=r"(r0), "=r"(r1), "=r"(r2), "=r"(r3) : "r"(addr));
}

__device__ __forceinline__ void ldsm4t(uint32_t& r0, uint32_t& r1,
                                       uint32_t& r2, uint32_t& r3, uint32_t addr)
{
    asm volatile("ldmatrix.sync.aligned.m8n8.x4.trans.shared.b16 {%0,%1,%2,%3}, [%4];"
                 : "=r"(r0), "=r"(r1), "=r"(r2), "=r"(r3) : "r"(addr));
}

__device__ __forceinline__ uint32_t smem_u32(const void* p) {
    uint32_t a;
    asm("{ .reg .u64 t; cvta.to.shared.u64 t, %1; cvt.u32.u64 %0, t; }"
        : "=r"(a) : "l"(p));
    return a;
}

__device__ __forceinline__ void cp16s(uint32_t smem_addr, const void* gptr) {
    asm volatile("cp.async.cg.shared.global [%0], [%1], 16;"
                 :: "r"(smem_addr), "l"(gptr));
}

// ---------------------------------------------------------------------------
// Merged fp32->fp16 convert for x, w_qkv, w_o in ONE launch.
// ---------------------------------------------------------------------------
#define N1 (MROWS * DD)
#define N2 (QKVN * DD)
#define N3 (DD * DD)
#define NTOT (N1 + N2 + N3)

__global__ __launch_bounds__(256) void cvt_all_kernel(
    const float* __restrict__ x, const float* __restrict__ wqkv,
    const float* __restrict__ wo,
    __half* __restrict__ dx, __half* __restrict__ dwqkv, __half* __restrict__ dwo)
{
    int i = (blockIdx.x * 256 + threadIdx.x) * 8;
    if (i >= NTOT) return;
    const float* src;
    __half* dst;
    if (i < N1)           { src = x + i;              dst = dx + i; }
    else if (i < N1 + N2) { src = wqkv + (i - N1);    dst = dwqkv + (i - N1); }
    else                  { src = wo + (i - N1 - N2); dst = dwo + (i - N1 - N2); }
    float4 v0 = *reinterpret_cast<const float4*>(src);
    float4 v1 = *reinterpret_cast<const float4*>(src + 4);
    uint4 u;
    u.x = pack_h2(v0.x, v0.y);
    u.y = pack_h2(v0.z, v0.w);
    u.z = pack_h2(v1.x, v1.y);
    u.w = pack_h2(v1.z, v1.w);
    *reinterpret_cast<uint4*>(dst) = u;
}

// ---------------------------------------------------------------------------
// fp16 GEMM (m16n8k16, fp32 accum), PERSISTENT chunk-pipelined:
// grid = min(ntiles, 296); each CTA walks its tiles as one continuous chunk
// stream; 3-stage cp.async ring prefetches ACROSS tile boundaries.
// 128x128 CTA tile, BK=64, 8 warps (4m x 2n), warp tile 32x64.
// ---------------------------------------------------------------------------
#define GH 72                      // halves per smem row (144 B stride)
#define STG_H (2 * 128 * GH)       // halves per stage (A block then W block)
#define D_ST 3
#define GSMB (D_ST * STG_H * 2)    // 110592 B

__global__ __launch_bounds__(256, 2) void gemm_f16_kernel(
    const __half* __restrict__ A, const __half* __restrict__ W,
    void* __restrict__ Cv, int M, int N, int K, int half_out)
{
    extern __shared__ __half gsm[];
    const uint32_t sb = smem_u32(gsm);

    const int tid  = threadIdx.x;
    const int warp = tid >> 5;
    const int lane = tid & 31;
    const int g    = lane >> 2;
    const int tc   = lane & 3;
    const int wm   = (warp >> 1) * 32;
    const int wn   = (warp & 1) * 64;

    const int ntx = N >> 7;
    const int NK  = K >> 6;
    const int ntiles = ntx * (M >> 7);
    const int G   = gridDim.x;
    const int nmine = (ntiles - (int)blockIdx.x + G - 1) / G;
    const int totc  = nmine * NK;

    const bool isW = tid >= 128;
    const int lrow = tid & 127;
    const uint32_t sof = (uint32_t)(((isW ? 128 * GH : 0) + lrow * GH) * 2);

    const uint32_t lqA = (uint32_t)(((lane & 15) * GH + (lane >> 4) * 8) * 2);
    const uint32_t lkB = (uint32_t)((((lane & 7) + (lane >> 4) * 8) * GH
                                    + ((lane >> 3) & 1) * 8) * 2);

    // issue chunk c into ring stage c % D_ST
    auto issue = [&](int c) {
        const int t  = (int)blockIdx.x + (c / NK) * G;
        const int k  = (c % NK) << 6;
        const int r0 = (isW ? (t % ntx) : (t / ntx)) * 128 + lrow;
        const __half* gp = (isW ? W : A) + (size_t)r0 * K + k;
        const uint32_t st = sb + (uint32_t)((c % D_ST) * STG_H * 2) + sof;
#pragma unroll
        for (int j = 0; j < 8; j++)
            cp16s(st + j * 16, gp + j * 8);
        asm volatile("cp.async.commit_group;");
    };

    float acc[2][8][4];
#pragma unroll
    for (int mf = 0; mf < 2; mf++)
#pragma unroll
        for (int nf = 0; nf < 8; nf++)
#pragma unroll
            for (int i = 0; i < 4; i++) acc[mf][nf][i] = 0.0f;

    if (totc > 0) issue(0);
    if (totc > 1) issue(1);

    for (int c = 0; c < totc; c++) {
        if (c < totc - 1) { asm volatile("cp.async.wait_group 1;"); }
        else              { asm volatile("cp.async.wait_group 0;"); }
        __syncthreads();

        if (c + 2 < totc) issue(c + 2);

        const uint32_t asb = sb + (uint32_t)((c % D_ST) * STG_H * 2);
        const uint32_t wsb = asb + (uint32_t)(128 * GH * 2);
#pragma unroll
        for (int kk = 0; kk < 4; kk++) {
            const uint32_t kbb = (uint32_t)(kk * 32);
            uint32_t a[2][4];
            ldsm4(a[0][0], a[0][1], a[0][2], a[0][3],
                  asb + (uint32_t)(wm * GH * 2) + lqA + kbb);
            ldsm4(a[1][0], a[1][1], a[1][2], a[1][3],
                  asb + (uint32_t)((wm + 16) * GH * 2) + lqA + kbb);
#pragma unroll
            for (int nb = 0; nb < 4; nb++) {
                uint32_t b00, b01, b10, b11;
                ldsm4(b00, b01, b10, b11,
                      wsb + (uint32_t)((wn + nb * 16) * GH * 2) + lkB + kbb);
                mma_f16(acc[0][2 * nb],     a[0][0], a[0][1], a[0][2], a[0][3], b00, b01);
                mma_f16(acc[1][2 * nb],     a[1][0], a[1][1], a[1][2], a[1][3], b00, b01);
                mma_f16(acc[0][2 * nb + 1], a[0][0], a[0][1], a[0][2], a[0][3], b10, b11);
                mma_f16(acc[1][2 * nb + 1], a[1][0], a[1][1], a[1][2], a[1][3], b10, b11);
            }
        }

        // tile finished: epilogue (overlaps next tile's in-flight loads)
        if ((c % NK) == NK - 1) {
            const int t  = (int)blockIdx.x + (c / NK) * G;
            const int m0 = (t / ntx) * 128;
            const int n0 = (t % ntx) * 128;
#pragma unroll
            for (int mf = 0; mf < 2; mf++) {
                const int r0 = m0 + wm + mf * 16 + g;
#pragma unroll
                for (int nf = 0; nf < 8; nf++) {
                    const int cc = n0 + wn + nf * 8 + 2 * tc;
                    if (half_out) {
                        __half* Ch = (__half*)Cv;
                        *reinterpret_cast<uint32_t*>(&Ch[(size_t)r0 * N + cc]) =
                            pack_h2(acc[mf][nf][0], acc[mf][nf][1]);
                        *reinterpret_cast<uint32_t*>(&Ch[(size_t)(r0 + 8) * N + cc]) =
                            pack_h2(acc[mf][nf][2], acc[mf][nf][3]);
                    } else {
                        float* Cf = (float*)Cv;
                        *reinterpret_cast<float2*>(&Cf[(size_t)r0 * N + cc]) =
                            make_float2(acc[mf][nf][0], acc[mf][nf][1]);
                        *reinterpret_cast<float2*>(&Cf[(size_t)(r0 + 8) * N + cc]) =
                            make_float2(acc[mf][nf][2], acc[mf][nf][3]);
                    }
                    acc[mf][nf][0] = 0.0f; acc[mf][nf][1] = 0.0f;
                    acc[mf][nf][2] = 0.0f; acc[mf][nf][3] = 0.0f;
                }
            }
        }
    }
}

// ---------------------------------------------------------------------------
// Flash attention, fp16 m16n8k16. 4-stage K/V ring, two tiles per barrier.
// NEW: softmax denominator l computed ON the tensor core (P @ ones column),
// carried as an alpha-rescaled accumulator fragment; P packed once.
// ---------------------------------------------------------------------------
#define BR 128
#define BC 64
#define NT (LL / BC)
#define QPH 72
#define QB   (BR * QPH * 2)
#define KSTB (BC * QPH * 2)
#define SB_K QB
#define SB_V (QB + 4 * KSTB)
#define ASM_BYTES (QB + 8 * KSTB)  // 92160 B -> 2 CTAs/SM

__global__ __launch_bounds__(256, 2) void attn_f16_kernel(
    const __half* __restrict__ qkv, __half* __restrict__ ctx)
{
    extern __shared__ uint32_t sm[];
    const uint32_t sb = smem_u32(sm);

    const int tid  = threadIdx.x;
    const int warp = tid >> 5;
    const int lane = tid & 31;
    const int g    = lane >> 2;
    const int tc   = lane & 3;
    const int wm   = warp * 16;

    const int bh = blockIdx.y;
    const int b  = bh >> 3;
    const int h  = bh & 7;
    const int q0 = blockIdx.x * BR;

    const __half* base = qkv + (size_t)b * LL * QKVN + h * DKK;

    const int lr  = tid >> 2;
    const int lc2 = (tid & 3) * 16;

    const uint32_t lqQ = (uint32_t)(((wm + (lane & 15)) * QPH + (lane >> 4) * 8) * 2);
    const uint32_t lkK = (uint32_t)((((lane & 7) + (lane >> 4) * 8) * QPH
                                    + ((lane >> 3) & 1) * 8) * 2);
    const uint32_t lvV = (uint32_t)((((lane & 7) + ((lane >> 3) & 1) * 8) * QPH
                                    + (lane >> 4) * 8) * 2);

    // ---- Prologue: Q + K/V tiles 0 and 1 ----
    {
        const int r   = tid >> 1;
        const int c0h = (tid & 1) * 32;
        const __half* qrow = base + (size_t)(q0 + r) * QKVN;
#pragma unroll
        for (int j = 0; j < 4; j++)
            cp16s(sb + (uint32_t)((r * QPH + c0h + 8 * j) * 2), qrow + c0h + 8 * j);

#pragma unroll
        for (int u = 0; u < 2; u++) {
            const __half* krow = base + (size_t)(u * BC + lr) * QKVN + DD;
            const __half* vrow = krow + DD;
            const uint32_t kd = sb + SB_K + (uint32_t)(u * KSTB);
            const uint32_t vd = sb + SB_V + (uint32_t)(u * KSTB);
#pragma unroll
            for (int j = 0; j < 2; j++) {
                cp16s(kd + (uint32_t)((lr * QPH + lc2 + 8 * j) * 2), krow + lc2 + 8 * j);
                cp16s(vd + (uint32_t)((lr * QPH + lc2 + 8 * j) * 2), vrow + lc2 + 8 * j);
            }
        }
        asm volatile("cp.async.commit_group;");
        asm volatile("cp.async.wait_group 0;");
    }
    __syncthreads();

    float oa[8][4];
#pragma unroll
    for (int n = 0; n < 8; n++)
#pragma unroll
        for (int i = 0; i < 4; i++) oa[n][i] = 0.0f;
    float la[4] = {0.0f, 0.0f, 0.0f, 0.0f};   // row-sum accumulator (l)
    float m0 = -1e30f, m1 = -1e30f;
    const uint32_t ONE2 = 0x3C003C00u;        // fp16 {1,1}

    for (int t = 0; t < NT; t += 2) {
        if (t + 2 < NT) {
#pragma unroll
            for (int u = 0; u < 2; u++) {
                const int tt = t + 2 + u;
                const __half* krow = base + (size_t)(tt * BC + lr) * QKVN + DD;
                const __half* vrow = krow + DD;
                const uint32_t kd = sb + SB_K + (uint32_t)((tt & 3) * KSTB);
                const uint32_t vd = sb + SB_V + (uint32_t)((tt & 3) * KSTB);
#pragma unroll
                for (int j = 0; j < 2; j++) {
                    cp16s(kd + (uint32_t)((lr * QPH + lc2 + 8 * j) * 2), krow + lc2 + 8 * j);
                    cp16s(vd + (uint32_t)((lr * QPH + lc2 + 8 * j) * 2), vrow + lc2 + 8 * j);
                }
            }
            asm volatile("cp.async.commit_group;");
        }

#pragma unroll
        for (int u = 0; u < 2; u++) {
            const int tt = t + u;
            const uint32_t ksb = sb + SB_K + (uint32_t)((tt & 3) * KSTB);
            const uint32_t vsb = sb + SB_V + (uint32_t)((tt & 3) * KSTB);

            // S = Q @ K^T
            float sa[8][4];
#pragma unroll
            for (int n = 0; n < 8; n++)
#pragma unroll
                for (int i = 0; i < 4; i++) sa[n][i] = 0.0f;

#pragma unroll
            for (int kk = 0; kk < 4; kk++) {
                uint32_t a0, a1, a2, a3;
                ldsm4(a0, a1, a2, a3, sb + lqQ + (uint32_t)(kk * 32));
#pragma unroll
                for (int nb = 0; nb < 4; nb++) {
                    uint32_t b00, b01, b10, b11;
                    ldsm4(b00, b01, b10, b11,
                          ksb + lkK + (uint32_t)((nb * 16 * QPH + kk * 16) * 2));
                    mma_f16(sa[2 * nb], a0, a1, a2, a3, b00, b01);
                    mma_f16(sa[2 * nb + 1], a0, a1, a2, a3, b10, b11);
                }
            }

            // Online softmax (base-2, scale inside exp argument)
            float mx0 = -1e30f, mx1 = -1e30f;
#pragma unroll
            for (int n = 0; n < 8; n++) {
                mx0 = fmaxf(mx0, fmaxf(sa[n][0], sa[n][1]));
                mx1 = fmaxf(mx1, fmaxf(sa[n][2], sa[n][3]));
            }
            mx0 = fmaxf(mx0, __shfl_xor_sync(0xffffffffu, mx0, 1));
            mx0 = fmaxf(mx0, __shfl_xor_sync(0xffffffffu, mx0, 2));
            mx1 = fmaxf(mx1, __shfl_xor_sync(0xffffffffu, mx1, 1));
            mx1 = fmaxf(mx1, __shfl_xor_sync(0xffffffffu, mx1, 2));

            const bool upd = !__all_sync(0xffffffffu, (mx0 <= m0) & (mx1 <= m1));
            if (upd) {
                float mn0 = fmaxf(m0, mx0);
                float mn1 = fmaxf(m1, mx1);
                float alpha0 = ex2(CC * (m0 - mn0));
                float alpha1 = ex2(CC * (m1 - mn1));
                m0 = mn0; m1 = mn1;
                la[0] *= alpha0; la[1] *= alpha0;
                la[2] *= alpha1; la[3] *= alpha1;
#pragma unroll
                for (int n = 0; n < 8; n++) {
                    oa[n][0] *= alpha0; oa[n][1] *= alpha0;
                    oa[n][2] *= alpha1; oa[n][3] *= alpha1;
                }
            }

            // exp + pack P fragments directly (no scalar sum; l via MMA below)
            const float nc0 = -CC * m0;
            const float nc1 = -CC * m1;
            uint32_t pa[8][2];
#pragma unroll
            for (int n = 0; n < 8; n++) {
                float p0 = ex2(fmaf(CC, sa[n][0], nc0));
                float p1 = ex2(fmaf(CC, sa[n][1], nc0));
                float p2 = ex2(fmaf(CC, sa[n][2], nc1));
                float p3 = ex2(fmaf(CC, sa[n][3], nc1));
                pa[n][0] = pack_h2(p0, p1);
                pa[n][1] = pack_h2(p2, p3);
            }

            // l += P @ ones (tensor-core row sum; cols of result identical)
#pragma unroll
            for (int kk = 0; kk < 4; kk++)
                mma_f16(la, pa[2 * kk][0], pa[2 * kk][1],
                            pa[2 * kk + 1][0], pa[2 * kk + 1][1], ONE2, ONE2);

            // O += P @ V
#pragma unroll
            for (int kk = 0; kk < 4; kk++) {
                uint32_t a0 = pa[2 * kk][0];
                uint32_t a1 = pa[2 * kk][1];
                uint32_t a2 = pa[2 * kk + 1][0];
                uint32_t a3 = pa[2 * kk + 1][1];
#pragma unroll
                for (int nb = 0; nb < 4; nb++) {
                    uint32_t b00, b01, b10, b11;
                    ldsm4t(b00, b01, b10, b11,
                           vsb + lvV + (uint32_t)((kk * 16 * QPH + nb * 16) * 2));
                    mma_f16(oa[2 * nb], a0, a1, a2, a3, b00, b01);
                    mma_f16(oa[2 * nb + 1], a0, a1, a2, a3, b10, b11);
                }
            }
        }

        asm volatile("cp.async.wait_group 0;");
        __syncthreads();
    }

    // Normalize and write ctx (l already complete per row; no reduction needed)
    float inv0 = 1.0f / la[0];
    float inv1 = 1.0f / la[2];

    const int r0 = q0 + wm + g;
    const int r1 = r0 + 8;
#pragma unroll
    for (int n = 0; n < 8; n++) {
        *reinterpret_cast<uint32_t*>(
            &ctx[(size_t)(b * LL + r0) * DD + h * DKK + n * 8 + 2 * tc]) =
            pack_h2(oa[n][0] * inv0, oa[n][1] * inv0);
        *reinterpret_cast<uint32_t*>(
            &ctx[(size_t)(b * LL + r1) * DD + h * DKK + n * 8 + 2 * tc]) =
            pack_h2(oa[n][2] * inv1, oa[n][3] * inv1);
    }
}

// ---------------------------------------------------------------------------
extern "C" void kernel_launch(void* const* d_in, const int* in_sizes, int n_in,
                              void* d_out, int out_size)
{
    const float* x     = (const float*)d_in[0];   // [B, L, D]
    const float* w_qkv = (const float*)d_in[1];   // [3D, D]
    const float* w_o   = (const float*)d_in[2];   // [D, D]
    float* out = (float*)d_out;                   // [B, L, D]

    __half *x_p, *wqkv_p, *wo_p, *qkv_p, *ctx_p;
    cudaGetSymbolAddress((void**)&x_p,    g_x);
    cudaGetSymbolAddress((void**)&wqkv_p, g_wqkv);
    cudaGetSymbolAddress((void**)&wo_p,   g_wo);
    cudaGetSymbolAddress((void**)&qkv_p,  g_qkv);
    cudaGetSymbolAddress((void**)&ctx_p,  g_ctx);
    cudaFuncSetAttribute(gemm_f16_kernel, cudaFuncAttributeMaxDynamicSharedMemorySize, GSMB);
    cudaFuncSetAttribute(attn_f16_kernel, cudaFuncAttributeMaxDynamicSharedMemorySize, ASM_BYTES);

    // 0) fp32 -> fp16 conversion, single launch for all three tensors
    cvt_all_kernel<<<(NTOT / 8 + 255) / 256, 256>>>(x, w_qkv, w_o, x_p, wqkv_p, wo_p);

    // 1) qkv = x @ w_qkv^T : [8192, 1536], fp16 out (persistent: 296 CTAs)
    {
        int ntiles = (QKVN / 128) * (MROWS / 128);   // 768
        int grid = ntiles < 296 ? ntiles : 296;
        gemm_f16_kernel<<<grid, 256, GSMB>>>(x_p, wqkv_p, qkv_p, MROWS, QKVN, DD, 1);
    }
    // 2) attention -> ctx (fp16)
    {
        dim3 grid(LL / BR, BB * HH);
        attn_f16_kernel<<<grid, 256, ASM_BYTES>>>(qkv_p, ctx_p);
    }
    // 3) out = ctx @ w_o^T : [8192, 512], fp32 out
    {
        int ntiles = (DD / 128) * (MROWS / 128);     // 256
        int grid = ntiles < 296 ? ntiles : 296;
        gemm_f16_kernel<<<grid, 256, GSMB>>>(ctx_p, wo_p, out, MROWS, DD, DD, 0);
    }
}

// round 16
// speedup vs baseline: 1.2607x; 1.2607x over previous
#include <cuda_runtime.h>
#include <cuda_fp16.h>
#include <math.h>
#include <stdint.h>

#define BB 2
#define LL 4096
#define DD 512
#define HH 8
#define DKK 64
#define MROWS (BB*LL)          // 8192
#define QKVN (3*DD)            // 1536
// softmax scale (1/sqrt(64) * log2(e)); applied inside exp2
#define CC (0.125f * 1.4426950408889634f)

// Scratch (allocation-free rule: __device__ globals)
__device__ __half g_x[(size_t)MROWS * DD];
__device__ __half g_wqkv[(size_t)QKVN * DD];
__device__ __half g_wo[(size_t)DD * DD];
__device__ __half g_qkv[(size_t)MROWS * QKVN];
__device__ __half g_ctx[(size_t)MROWS * DD];

// ---------------------------------------------------------------------------
// Helpers
// ---------------------------------------------------------------------------
__device__ __forceinline__ float ex2(float x) {
    float y;
    asm("ex2.approx.ftz.f32 %0, %1;" : "=f"(y) : "f"(x));
    return y;
}

__device__ __forceinline__ uint32_t pack_h2(float lo, float hi) {
    uint32_t r;
    asm("cvt.rn.f16x2.f32 %0, %1, %2;" : "=r"(r) : "f"(hi), "f"(lo));
    return r;
}

__device__ __forceinline__ void mma_f16(float c[4],
    uint32_t a0, uint32_t a1, uint32_t a2, uint32_t a3,
    uint32_t b0, uint32_t b1)
{
    asm volatile(
        "mma.sync.aligned.m16n8k16.row.col.f32.f16.f16.f32 "
        "{%0,%1,%2,%3}, {%4,%5,%6,%7}, {%8,%9}, {%0,%1,%2,%3};"
        : "+f"(c[0]), "+f"(c[1]), "+f"(c[2]), "+f"(c[3])
        : "r"(a0), "r"(a1), "r"(a2), "r"(a3), "r"(b0), "r"(b1));
}

__device__ __forceinline__ void ldsm4(uint32_t& r0, uint32_t& r1,
                                      uint32_t& r2, uint32_t& r3, uint32_t addr)
{
    asm volatile("ldmatrix.sync.aligned.m8n8.x4.shared.b16 {%0,%1,%2,%3}, [%4];"
                 : "=r"(r0), "=r"(r1), "=r"(r2), "=r"(r3) : "r"(addr));
}

__device__ __forceinline__ void ldsm4t(uint32_t& r0, uint32_t& r1,
                                       uint32_t& r2, uint32_t& r3, uint32_t addr)
{
    asm volatile("ldmatrix.sync.aligned.m8n8.x4.trans.shared.b16 {%0,%1,%2,%3}, [%4];"
                 : "=r"(r0), "=r"(r1), "=r"(r2), "=r"(r3) : "r"(addr));
}

__device__ __forceinline__ uint32_t smem_u32(const void* p) {
    uint32_t a;
    asm("{ .reg .u64 t; cvta.to.shared.u64 t, %1; cvt.u32.u64 %0, t; }"
        : "=r"(a) : "l"(p));
    return a;
}

__device__ __forceinline__ void cp16s(uint32_t smem_addr, const void* gptr) {
    asm volatile("cp.async.cg.shared.global [%0], [%1], 16;"
                 :: "r"(smem_addr), "l"(gptr));
}

// ---------------------------------------------------------------------------
// Merged fp32->fp16 convert for x, w_qkv, w_o in ONE launch.
// ---------------------------------------------------------------------------
#define N1 (MROWS * DD)
#define N2 (QKVN * DD)
#define N3 (DD * DD)
#define NTOT (N1 + N2 + N3)

__global__ __launch_bounds__(256) void cvt_all_kernel(
    const float* __restrict__ x, const float* __restrict__ wqkv,
    const float* __restrict__ wo,
    __half* __restrict__ dx, __half* __restrict__ dwqkv, __half* __restrict__ dwo)
{
    int i = (blockIdx.x * 256 + threadIdx.x) * 8;
    if (i >= NTOT) return;
    const float* src;
    __half* dst;
    if (i < N1)           { src = x + i;              dst = dx + i; }
    else if (i < N1 + N2) { src = wqkv + (i - N1);    dst = dwqkv + (i - N1); }
    else                  { src = wo + (i - N1 - N2); dst = dwo + (i - N1 - N2); }
    float4 v0 = *reinterpret_cast<const float4*>(src);
    float4 v1 = *reinterpret_cast<const float4*>(src + 4);
    uint4 u;
    u.x = pack_h2(v0.x, v0.y);
    u.y = pack_h2(v0.z, v0.w);
    u.z = pack_h2(v1.x, v1.y);
    u.w = pack_h2(v1.z, v1.w);
    *reinterpret_cast<uint4*>(dst) = u;
}

// ---------------------------------------------------------------------------
// fp16 GEMM (m16n8k16, fp32 accum), 3-stage cp.async pipeline, BK=64:
// C[M,N] = A[M,K] @ W[N,K]^T. CTA tile 128x256, 512 threads = 16 warps
// (4m x 4n), warp tile 32x64. Staged traffic per output element is 25% lower
// than 128x128 tiles (cp.async issue-rate is the binding resource).
// ---------------------------------------------------------------------------
#define GH 72                          // halves per smem row (144 B stride)
#define GSTG_H ((128 + 256) * GH)      // halves per stage: A block + W block
#define D_ST 3
#define GSMB (D_ST * GSTG_H * 2)       // 165888 B

__global__ __launch_bounds__(512, 1) void gemm_f16_kernel(
    const __half* __restrict__ A, const __half* __restrict__ W,
    void* __restrict__ Cv, int M, int N, int K, int half_out)
{
    extern __shared__ __half gsm[];
    const uint32_t sb = smem_u32(gsm);

    const int tid  = threadIdx.x;
    const int warp = tid >> 5;
    const int lane = tid & 31;
    const int g    = lane >> 2;
    const int tc   = lane & 3;
    const int wm   = (warp >> 2) * 32;   // 4 m-groups
    const int wn   = (warp & 3) * 64;    // 4 n-groups
    const int m0   = blockIdx.y * 128;
    const int n0   = blockIdx.x * 256;

    // loader mapping: 512 threads, 384 rows/chunk (128 A + 256 W), 8 segs/row
    const int lr0 = tid >> 3;            // 0..63
    const int sg  = (tid & 7) * 8;       // half offset within 64

    const uint32_t lqA = (uint32_t)(((lane & 15) * GH + (lane >> 4) * 8) * 2);
    const uint32_t lkB = (uint32_t)((((lane & 7) + (lane >> 4) * 8) * GH
                                    + ((lane >> 3) & 1) * 8) * 2);

    float acc[2][8][4];
#pragma unroll
    for (int mf = 0; mf < 2; mf++)
#pragma unroll
        for (int nf = 0; nf < 8; nf++)
#pragma unroll
            for (int i = 0; i < 4; i++) acc[mf][nf][i] = 0.0f;

    const int NK = K >> 6;   // BK=64 chunks

    // issue chunk i into ring stage i % D_ST (6 cp16 per thread)
    auto issue = [&](int i) {
        const int k0 = i << 6;
        const uint32_t st = sb + (uint32_t)((i % D_ST) * GSTG_H * 2);
#pragma unroll
        for (int s = 0; s < 2; s++) {          // A rows 0..127
            const int row = s * 64 + lr0;
            cp16s(st + (uint32_t)((row * GH + sg) * 2),
                  A + (size_t)(m0 + row) * K + k0 + sg);
        }
#pragma unroll
        for (int s = 0; s < 4; s++) {          // W rows 0..255
            const int row = s * 64 + lr0;
            cp16s(st + (uint32_t)(((128 + row) * GH + sg) * 2),
                  W + (size_t)(n0 + row) * K + k0 + sg);
        }
        asm volatile("cp.async.commit_group;");
    };

    issue(0);
    if (NK > 1) issue(1);

    for (int i = 0; i < NK; i++) {
        if (i < NK - 1) { asm volatile("cp.async.wait_group 1;"); }
        else            { asm volatile("cp.async.wait_group 0;"); }
        __syncthreads();

        if (i + 2 < NK) issue(i + 2);

        const uint32_t asb = sb + (uint32_t)((i % D_ST) * GSTG_H * 2);
        const uint32_t wsb = asb + (uint32_t)(128 * GH * 2);
#pragma unroll
        for (int kk = 0; kk < 4; kk++) {
            const uint32_t kbb = (uint32_t)(kk * 32);   // 16 halves
            uint32_t a[2][4];
            ldsm4(a[0][0], a[0][1], a[0][2], a[0][3],
                  asb + (uint32_t)(wm * GH * 2) + lqA + kbb);
            ldsm4(a[1][0], a[1][1], a[1][2], a[1][3],
                  asb + (uint32_t)((wm + 16) * GH * 2) + lqA + kbb);
#pragma unroll
            for (int nb = 0; nb < 4; nb++) {
                uint32_t b00, b01, b10, b11;
                ldsm4(b00, b01, b10, b11,
                      wsb + (uint32_t)((wn + nb * 16) * GH * 2) + lkB + kbb);
                mma_f16(acc[0][2 * nb],     a[0][0], a[0][1], a[0][2], a[0][3], b00, b01);
                mma_f16(acc[1][2 * nb],     a[1][0], a[1][1], a[1][2], a[1][3], b00, b01);
                mma_f16(acc[0][2 * nb + 1], a[0][0], a[0][1], a[0][2], a[0][3], b10, b11);
                mma_f16(acc[1][2 * nb + 1], a[1][0], a[1][1], a[1][2], a[1][3], b10, b11);
            }
        }
    }

#pragma unroll
    for (int mf = 0; mf < 2; mf++) {
        const int r0 = m0 + wm + mf * 16 + g;
#pragma unroll
        for (int nf = 0; nf < 8; nf++) {
            const int cc = n0 + wn + nf * 8 + 2 * tc;
            if (half_out) {
                __half* Ch = (__half*)Cv;
                *reinterpret_cast<uint32_t*>(&Ch[(size_t)r0 * N + cc]) =
                    pack_h2(acc[mf][nf][0], acc[mf][nf][1]);
                *reinterpret_cast<uint32_t*>(&Ch[(size_t)(r0 + 8) * N + cc]) =
                    pack_h2(acc[mf][nf][2], acc[mf][nf][3]);
            } else {
                float* Cf = (float*)Cv;
                *reinterpret_cast<float2*>(&Cf[(size_t)r0 * N + cc]) =
                    make_float2(acc[mf][nf][0], acc[mf][nf][1]);
                *reinterpret_cast<float2*>(&Cf[(size_t)(r0 + 8) * N + cc]) =
                    make_float2(acc[mf][nf][2], acc[mf][nf][3]);
            }
        }
    }
}

// ---------------------------------------------------------------------------
// Flash attention, fp16 m16n8k16. BR=256 (512 threads, 16 warps x 16 rows),
// halving the K/V re-staging vs BR=128 (cp.async issue is the binding
// resource). Per-warp math identical to the R13-verified kernel: 4-stage K/V
// ring, two tiles per barrier, scalar l with quad shuffles.
// ---------------------------------------------------------------------------
#define BR 256
#define BC 64
#define NT (LL / BC)
#define QPH 72
#define QB   (BR * QPH * 2)        // 36864 B  Q tile
#define KSTB (BC * QPH * 2)        // 9216 B per K/V stage
#define SB_K QB
#define SB_V (QB + 4 * KSTB)
#define ASM_BYTES (QB + 8 * KSTB)  // 110592 B

__global__ __launch_bounds__(512, 1) void attn_f16_kernel(
    const __half* __restrict__ qkv, __half* __restrict__ ctx)
{
    extern __shared__ uint32_t sm[];
    const uint32_t sb = smem_u32(sm);

    const int tid  = threadIdx.x;
    const int warp = tid >> 5;
    const int lane = tid & 31;
    const int g    = lane >> 2;
    const int tc   = lane & 3;
    const int wm   = warp * 16;        // 16 warps x 16 rows = 256

    const int bh = blockIdx.y;
    const int b  = bh >> 3;
    const int h  = bh & 7;
    const int q0 = blockIdx.x * BR;

    const __half* base = qkv + (size_t)b * LL * QKVN + h * DKK;

    // K/V loader mapping: 512 threads -> 64 rows x 8 segs, 1 cp16 per matrix
    const int lvr = tid >> 3;          // 0..63
    const int lsg = (tid & 7) * 8;     // half offset

    const uint32_t lqQ = (uint32_t)(((wm + (lane & 15)) * QPH + (lane >> 4) * 8) * 2);
    const uint32_t lkK = (uint32_t)((((lane & 7) + (lane >> 4) * 8) * QPH
                                    + ((lane >> 3) & 1) * 8) * 2);
    const uint32_t lvV = (uint32_t)((((lane & 7) + ((lane >> 3) & 1) * 8) * QPH
                                    + (lane >> 4) * 8) * 2);

    // ---- Prologue: Q (256x64) + K/V tiles 0 and 1 ----
    {
        const int r   = tid >> 1;               // 0..255
        const int c0h = (tid & 1) * 32;
        const __half* qrow = base + (size_t)(q0 + r) * QKVN;
#pragma unroll
        for (int j = 0; j < 4; j++)
            cp16s(sb + (uint32_t)((r * QPH + c0h + 8 * j) * 2), qrow + c0h + 8 * j);

#pragma unroll
        for (int u = 0; u < 2; u++) {
            const __half* krow = base + (size_t)(u * BC + lvr) * QKVN + DD;
            const __half* vrow = krow + DD;
            cp16s(sb + SB_K + (uint32_t)(u * KSTB) + (uint32_t)((lvr * QPH + lsg) * 2), krow + lsg);
            cp16s(sb + SB_V + (uint32_t)(u * KSTB) + (uint32_t)((lvr * QPH + lsg) * 2), vrow + lsg);
        }
        asm volatile("cp.async.commit_group;");
        asm volatile("cp.async.wait_group 0;");
    }
    __syncthreads();

    float oa[8][4];
#pragma unroll
    for (int n = 0; n < 8; n++)
#pragma unroll
        for (int i = 0; i < 4; i++) oa[n][i] = 0.0f;
    float m0 = -1e30f, m1 = -1e30f;
    float l0 = 0.0f,  l1 = 0.0f;

    for (int t = 0; t < NT; t += 2) {
        if (t + 2 < NT) {
#pragma unroll
            for (int u = 0; u < 2; u++) {
                const int tt = t + 2 + u;
                const __half* krow = base + (size_t)(tt * BC + lvr) * QKVN + DD;
                const __half* vrow = krow + DD;
                const uint32_t kd = sb + SB_K + (uint32_t)((tt & 3) * KSTB);
                const uint32_t vd = sb + SB_V + (uint32_t)((tt & 3) * KSTB);
                cp16s(kd + (uint32_t)((lvr * QPH + lsg) * 2), krow + lsg);
                cp16s(vd + (uint32_t)((lvr * QPH + lsg) * 2), vrow + lsg);
            }
            asm volatile("cp.async.commit_group;");
        }

#pragma unroll
        for (int u = 0; u < 2; u++) {
            const int tt = t + u;
            const uint32_t ksb = sb + SB_K + (uint32_t)((tt & 3) * KSTB);
            const uint32_t vsb = sb + SB_V + (uint32_t)((tt & 3) * KSTB);

            // S = Q @ K^T : 16x64 per warp
            float sa[8][4];
#pragma unroll
            for (int n = 0; n < 8; n++)
#pragma unroll
                for (int i = 0; i < 4; i++) sa[n][i] = 0.0f;

#pragma unroll
            for (int kk = 0; kk < 4; kk++) {
                uint32_t a0, a1, a2, a3;
                ldsm4(a0, a1, a2, a3, sb + lqQ + (uint32_t)(kk * 32));
#pragma unroll
                for (int nb = 0; nb < 4; nb++) {
                    uint32_t b00, b01, b10, b11;
                    ldsm4(b00, b01, b10, b11,
                          ksb + lkK + (uint32_t)((nb * 16 * QPH + kk * 16) * 2));
                    mma_f16(sa[2 * nb], a0, a1, a2, a3, b00, b01);
                    mma_f16(sa[2 * nb + 1], a0, a1, a2, a3, b10, b11);
                }
            }

            // Online softmax (base-2, scale inside exp argument)
            float mx0 = -1e30f, mx1 = -1e30f;
#pragma unroll
            for (int n = 0; n < 8; n++) {
                mx0 = fmaxf(mx0, fmaxf(sa[n][0], sa[n][1]));
                mx1 = fmaxf(mx1, fmaxf(sa[n][2], sa[n][3]));
            }
            mx0 = fmaxf(mx0, __shfl_xor_sync(0xffffffffu, mx0, 1));
            mx0 = fmaxf(mx0, __shfl_xor_sync(0xffffffffu, mx0, 2));
            mx1 = fmaxf(mx1, __shfl_xor_sync(0xffffffffu, mx1, 1));
            mx1 = fmaxf(mx1, __shfl_xor_sync(0xffffffffu, mx1, 2));

            const bool upd = !__all_sync(0xffffffffu, (mx0 <= m0) & (mx1 <= m1));
            if (upd) {
                float mn0 = fmaxf(m0, mx0);
                float mn1 = fmaxf(m1, mx1);
                float alpha0 = ex2(CC * (m0 - mn0));
                float alpha1 = ex2(CC * (m1 - mn1));
                m0 = mn0; m1 = mn1;
                l0 *= alpha0;
                l1 *= alpha1;
#pragma unroll
                for (int n = 0; n < 8; n++) {
                    oa[n][0] *= alpha0; oa[n][1] *= alpha0;
                    oa[n][2] *= alpha1; oa[n][3] *= alpha1;
                }
            }

            const float nc0 = -CC * m0;
            const float nc1 = -CC * m1;
            float sum0 = 0.0f, sum1 = 0.0f;
#pragma unroll
            for (int n = 0; n < 8; n++) {
                float p0 = ex2(fmaf(CC, sa[n][0], nc0));
                float p1 = ex2(fmaf(CC, sa[n][1], nc0));
                float p2 = ex2(fmaf(CC, sa[n][2], nc1));
                float p3 = ex2(fmaf(CC, sa[n][3], nc1));
                sum0 += p0 + p1;
                sum1 += p2 + p3;
                sa[n][0] = p0; sa[n][1] = p1; sa[n][2] = p2; sa[n][3] = p3;
            }
            l0 += sum0;
            l1 += sum1;

            // O += P @ V
#pragma unroll
            for (int kk = 0; kk < 4; kk++) {
                uint32_t a0 = pack_h2(sa[2 * kk][0],     sa[2 * kk][1]);
                uint32_t a1 = pack_h2(sa[2 * kk][2],     sa[2 * kk][3]);
                uint32_t a2 = pack_h2(sa[2 * kk + 1][0], sa[2 * kk + 1][1]);
                uint32_t a3 = pack_h2(sa[2 * kk + 1][2], sa[2 * kk + 1][3]);
#pragma unroll
                for (int nb = 0; nb < 4; nb++) {
                    uint32_t b00, b01, b10, b11;
                    ldsm4t(b00, b01, b10, b11,
                           vsb + lvV + (uint32_t)((kk * 16 * QPH + nb * 16) * 2));
                    mma_f16(oa[2 * nb], a0, a1, a2, a3, b00, b01);
                    mma_f16(oa[2 * nb + 1], a0, a1, a2, a3, b10, b11);
                }
            }
        }

        asm volatile("cp.async.wait_group 0;");
        __syncthreads();
    }

    // Finalize l, normalize, write ctx (fp16)
    l0 += __shfl_xor_sync(0xffffffffu, l0, 1);
    l0 += __shfl_xor_sync(0xffffffffu, l0, 2);
    l1 += __shfl_xor_sync(0xffffffffu, l1, 1);
    l1 += __shfl_xor_sync(0xffffffffu, l1, 2);
    float inv0 = 1.0f / l0;
    float inv1 = 1.0f / l1;

    const int r0 = q0 + wm + g;
    const int r1 = r0 + 8;
#pragma unroll
    for (int n = 0; n < 8; n++) {
        *reinterpret_cast<uint32_t*>(
            &ctx[(size_t)(b * LL + r0) * DD + h * DKK + n * 8 + 2 * tc]) =
            pack_h2(oa[n][0] * inv0, oa[n][1] * inv0);
        *reinterpret_cast<uint32_t*>(
            &ctx[(size_t)(b * LL + r1) * DD + h * DKK + n * 8 + 2 * tc]) =
            pack_h2(oa[n][2] * inv1, oa[n][3] * inv1);
    }
}

// ---------------------------------------------------------------------------
extern "C" void kernel_launch(void* const* d_in, const int* in_sizes, int n_in,
                              void* d_out, int out_size)
{
    const float* x     = (const float*)d_in[0];   // [B, L, D]
    const float* w_qkv = (const float*)d_in[1];   // [3D, D]
    const float* w_o   = (const float*)d_in[2];   // [D, D]
    float* out = (float*)d_out;                   // [B, L, D]

    __half *x_p, *wqkv_p, *wo_p, *qkv_p, *ctx_p;
    cudaGetSymbolAddress((void**)&x_p,    g_x);
    cudaGetSymbolAddress((void**)&wqkv_p, g_wqkv);
    cudaGetSymbolAddress((void**)&wo_p,   g_wo);
    cudaGetSymbolAddress((void**)&qkv_p,  g_qkv);
    cudaGetSymbolAddress((void**)&ctx_p,  g_ctx);
    cudaFuncSetAttribute(gemm_f16_kernel, cudaFuncAttributeMaxDynamicSharedMemorySize, GSMB);
    cudaFuncSetAttribute(attn_f16_kernel, cudaFuncAttributeMaxDynamicSharedMemorySize, ASM_BYTES);

    // 0) fp32 -> fp16 conversion, single launch for all three tensors
    cvt_all_kernel<<<(NTOT / 8 + 255) / 256, 256>>>(x, w_qkv, w_o, x_p, wqkv_p, wo_p);

    // 1) qkv = x @ w_qkv^T : [8192, 1536], fp16 out
    {
        dim3 grid(QKVN / 256, MROWS / 128);   // 6 x 64
        gemm_f16_kernel<<<grid, 512, GSMB>>>(x_p, wqkv_p, qkv_p, MROWS, QKVN, DD, 1);
    }
    // 2) attention -> ctx (fp16)
    {
        dim3 grid(LL / BR, BB * HH);          // 16 x 16
        attn_f16_kernel<<<grid, 512, ASM_BYTES>>>(qkv_p, ctx_p);
    }
    // 3) out = ctx @ w_o^T : [8192, 512], fp32 out
    {
        dim3 grid(DD / 256, MROWS / 128);     // 2 x 64
        gemm_f16_kernel<<<grid, 512, GSMB>>>(ctx_p, wo_p, out, MROWS, DD, DD, 0);
    }
}